// round 6
// baseline (speedup 1.0000x reference)
#include <cuda_runtime.h>
#include <mma.h>
#include <cstdint>

using namespace nvcuda;

// ---------------------------------------------------------------------------
// Problem constants
// ---------------------------------------------------------------------------
#define B_   32
#define LQ_  300
#define D_   256
#define H_   8
#define L_   3
#define P_   4
#define HD_  32
#define LV_  8400   // 80*80 + 40*40 + 20*20
#define NQF  320    // padded fused off|attn width (192 off + 96 attn + 32 pad)

// ---------------------------------------------------------------------------
// Scratch (device globals)
// ---------------------------------------------------------------------------
__device__ float g_qf  [(size_t)B_ * LQ_ * NQF];          // [9600,320]
__device__ float g_raw [(size_t)B_ * LQ_ * H_ * D_];      // [9600, 8, 256]
__device__ float g_wsum[(size_t)B_ * LQ_ * H_];           // [9600, 8]
__device__ float g_samp[(size_t)B_ * LQ_ * D_];           // [9600, 256]
__device__ float g_Wqf [256 * NQF];
__device__ float g_bqf [NQF];

// ---------------------------------------------------------------------------
// Build fused (padded) query-side weights: Wqf[256,320] = [Woff | Wattn | 0]
// ---------------------------------------------------------------------------
__global__ __launch_bounds__(256)
void prep_weights_kernel(const float* __restrict__ Woff, const float* __restrict__ boff,
                         const float* __restrict__ Wattn, const float* __restrict__ battn,
                         float* __restrict__ Wqf, float* __restrict__ bqf)
{
    int i = blockIdx.x * blockDim.x + threadIdx.x;
    if (i < 256 * NQF) {
        int k = i / NQF, j = i % NQF;
        float v = 0.f;
        if (j < 192)      v = Woff[k * 192 + j];
        else if (j < 288) v = Wattn[k * 96 + (j - 192)];
        Wqf[i] = v;
    }
    if (i < NQF) {
        float v = 0.f;
        if (i < 192)      v = boff[i];
        else if (i < 288) v = battn[i - 192];
        bqf[i] = v;
    }
}

// ---------------------------------------------------------------------------
// tf32 helpers
// ---------------------------------------------------------------------------
__device__ __forceinline__ float to_tf32(float x) {
    float r;
    asm("cvt.rna.tf32.f32 %0, %1;" : "=f"(r) : "f"(x));
    return r;
}

// ---------------------------------------------------------------------------
// 3xTF32 GEMM (fp32-accurate): C[M,N] = A[M,K] @ B[K,N] + bias
//   BM=128, BN = BN_T (64 or 32), BK=32, 256 threads, wmma m16n16k8.
//   a*b ~= a_hi*b_hi + a_hi*b_lo + a_lo*b_hi   (error ~2^-22 per product)
// blockIdx.z adds per-slice offsets (zA/zB/zBias/zWs/zC) for the per-head
// block-diagonal projection. WS_BIAS: C += ws[m]*bias[n] instead of +bias[n].
// Requires M%128==0, N%BN_T==0, K%32==0; all pointers 16B-aligned.
// ---------------------------------------------------------------------------
template<int BN_T, bool WS_BIAS>
__global__ __launch_bounds__(256)
void gemm_tf32_kernel(const float* __restrict__ A, int lda, int zA,
                      const float* __restrict__ Bm, int ldb, int zB,
                      const float* __restrict__ bias, int zBias,
                      const float* __restrict__ ws, int ldws, int zWs,
                      float* __restrict__ C, int ldc, int zC, int K)
{
    constexpr int MI  = (BN_T == 64) ? 2 : 1;   // m16 tiles per warp
    constexpr int LDA = 36;                     // padded k-width
    constexpr int LDB = BN_T + 4;
    constexpr int LDC = BN_T + 4;

    // smem: As_hi/As_lo, reused as Cs in the epilogue
    __shared__ __align__(16) float smbuf[128 * LDA * 2];      // 36 KB
    __shared__ __align__(16) float Bs_hi[32][LDB];
    __shared__ __align__(16) float Bs_lo[32][LDB];
    float (*As_hi)[LDA] = (float(*)[LDA])smbuf;
    float (*As_lo)[LDA] = (float(*)[LDA])(smbuf + 128 * LDA);
    float (*Cs)[LDC]    = (float(*)[LDC])smbuf;

    const int z = blockIdx.z;
    A    += (size_t)z * zA;
    Bm   += (size_t)z * zB;
    bias += (size_t)z * zBias;
    if (WS_BIAS) ws += (size_t)z * zWs;
    C    += (size_t)z * zC;

    const int tid = threadIdx.x;
    const int m0  = blockIdx.y * 128;
    const int n0  = blockIdx.x * BN_T;
    const int w   = tid >> 5;

    const int warp_m = (BN_T == 64) ? (w >> 1) * 32 : w * 16;
    const int warp_n = (BN_T == 64) ? (w & 1) * 32 : 0;

    wmma::fragment<wmma::accumulator, 16, 16, 8, float> acc[MI][2];
#pragma unroll
    for (int mi = 0; mi < MI; mi++)
#pragma unroll
        for (int ni = 0; ni < 2; ni++)
            wmma::fill_fragment(acc[mi][ni], 0.f);

    constexpr int NB4 = BN_T / 4;               // float4 per B row

    for (int k0 = 0; k0 < K; k0 += 32) {
        // --- stage A tile 128x32 as hi/lo ---
#pragma unroll
        for (int t = 0; t < 4; t++) {
            int idx = tid + t * 256;            // < 1024
            int row = idx >> 3, q = idx & 7;
            float4 v = *(const float4*)(A + (size_t)(m0 + row) * lda + k0 + q * 4);
            float4 hi, lo;
            hi.x = to_tf32(v.x); lo.x = v.x - hi.x;
            hi.y = to_tf32(v.y); lo.y = v.y - hi.y;
            hi.z = to_tf32(v.z); lo.z = v.z - hi.z;
            hi.w = to_tf32(v.w); lo.w = v.w - hi.w;
            *(float4*)&As_hi[row][q * 4] = hi;
            *(float4*)&As_lo[row][q * 4] = lo;
        }
        // --- stage B tile 32xBN as hi/lo ---
#pragma unroll
        for (int t = 0; t < (32 * NB4) / 256; t++) {
            int idx = tid + t * 256;
            int k = idx / NB4, qn = idx % NB4;
            float4 v = *(const float4*)(Bm + (size_t)(k0 + k) * ldb + n0 + qn * 4);
            float4 hi, lo;
            hi.x = to_tf32(v.x); lo.x = v.x - hi.x;
            hi.y = to_tf32(v.y); lo.y = v.y - hi.y;
            hi.z = to_tf32(v.z); lo.z = v.z - hi.z;
            hi.w = to_tf32(v.w); lo.w = v.w - hi.w;
            *(float4*)&Bs_hi[k][qn * 4] = hi;
            *(float4*)&Bs_lo[k][qn * 4] = lo;
        }
        __syncthreads();

#pragma unroll
        for (int kk = 0; kk < 32; kk += 8) {
            wmma::fragment<wmma::matrix_a, 16, 16, 8, wmma::precision::tf32, wmma::row_major> a_hi[MI], a_lo[MI];
            wmma::fragment<wmma::matrix_b, 16, 16, 8, wmma::precision::tf32, wmma::row_major> b_hi[2], b_lo[2];
#pragma unroll
            for (int mi = 0; mi < MI; mi++) {
                wmma::load_matrix_sync(a_hi[mi], &As_hi[warp_m + mi * 16][kk], LDA);
                wmma::load_matrix_sync(a_lo[mi], &As_lo[warp_m + mi * 16][kk], LDA);
            }
#pragma unroll
            for (int ni = 0; ni < 2; ni++) {
                wmma::load_matrix_sync(b_hi[ni], &Bs_hi[kk][warp_n + ni * 16], LDB);
                wmma::load_matrix_sync(b_lo[ni], &Bs_lo[kk][warp_n + ni * 16], LDB);
            }
#pragma unroll
            for (int mi = 0; mi < MI; mi++)
#pragma unroll
                for (int ni = 0; ni < 2; ni++) {
                    wmma::mma_sync(acc[mi][ni], a_hi[mi], b_hi[ni], acc[mi][ni]);
                    wmma::mma_sync(acc[mi][ni], a_hi[mi], b_lo[ni], acc[mi][ni]);
                    wmma::mma_sync(acc[mi][ni], a_lo[mi], b_hi[ni], acc[mi][ni]);
                }
        }
        __syncthreads();
    }

    // --- epilogue: park accumulators in smem (aliases As), add bias, write ---
#pragma unroll
    for (int mi = 0; mi < MI; mi++)
#pragma unroll
        for (int ni = 0; ni < 2; ni++)
            wmma::store_matrix_sync(&Cs[warp_m + mi * 16][warp_n + ni * 16],
                                    acc[mi][ni], LDC, wmma::mem_row_major);
    __syncthreads();

#pragma unroll
    for (int t = 0; t < (128 * NB4) / 256; t++) {
        int idx = tid + t * 256;
        int m = idx / NB4, qn = idx % NB4;
        float4 cv = *(const float4*)&Cs[m][qn * 4];
        float4 bb = *(const float4*)(bias + n0 + qn * 4);
        float s = 1.f;
        if (WS_BIAS) s = ws[(size_t)(m0 + m) * ldws];
        cv.x += s * bb.x; cv.y += s * bb.y; cv.z += s * bb.z; cv.w += s * bb.w;
        *(float4*)(C + (size_t)(m0 + m) * ldc + n0 + qn * 4) = cv;
    }
}

// ---------------------------------------------------------------------------
// Sampling kernel (gather only): warp <-> head, CTA <-> (b,q).
// ---------------------------------------------------------------------------
__global__ __launch_bounds__(256)
void sample_raw_kernel(const float* __restrict__ rp,
                       const float* __restrict__ qf,     // [9600,320] off|attn
                       const float* __restrict__ value,  // [B, LV, 256] fp32
                       float* __restrict__ raw,          // [9600, 8, 256]
                       float* __restrict__ wsumb)        // [9600, 8]
{
    const int bq   = blockIdx.x;
    const int h    = threadIdx.x >> 5;
    const int lane = threadIdx.x & 31;
    const int b    = bq / LQ_;

    const float* al = qf + (size_t)bq * NQF + 192 + h * (L_ * P_);
    float w[L_ * P_];
    float mx = -1e30f;
#pragma unroll
    for (int i = 0; i < L_ * P_; i++) { w[i] = al[i]; mx = fmaxf(mx, w[i]); }
    float ssum = 0.f;
#pragma unroll
    for (int i = 0; i < L_ * P_; i++) { w[i] = __expf(w[i] - mx); ssum += w[i]; }
    const float inv = 1.f / ssum;

    const float* offp = qf + (size_t)bq * NQF + h * (L_ * P_ * 2);
    const float* rpp  = rp + (size_t)bq * (L_ * 4);
    const float4* vb  = (const float4*)(value + (size_t)b * LV_ * D_);

    float4 a0 = make_float4(0.f, 0.f, 0.f, 0.f);
    float4 a1 = make_float4(0.f, 0.f, 0.f, 0.f);
    float wsum = 0.f;

    const int HsA[3] = {80, 40, 20};
    const int stA[3] = {0, 6400, 8000};

#pragma unroll
    for (int l = 0; l < L_; l++) {
        const float cx = rpp[l * 4 + 0];
        const float cy = rpp[l * 4 + 1];
        const float hw = rpp[l * 4 + 2] * 0.5f;
        const float hh = rpp[l * 4 + 3] * 0.5f;
        const int Wl = HsA[l], Hl = HsA[l], s0 = stA[l];

#pragma unroll
        for (int p = 0; p < P_; p++) {
            const float lx = cx + offp[(l * P_ + p) * 2 + 0] * hw;
            const float ly = cy + offp[(l * P_ + p) * 2 + 1] * hh;
            const float x = lx * (float)Wl - 0.5f;
            const float y = ly * (float)Hl - 0.5f;
            const float x0f = floorf(x), y0f = floorf(y);
            const int   x0 = (int)x0f,  y0 = (int)y0f;
            const float wx1 = x - x0f, wx0 = 1.f - wx1;
            const float wy1 = y - y0f, wy0 = 1.f - wy1;
            const float aw = w[l * P_ + p] * inv;

            const float fx0 = (x0 >= 0 && x0 < Wl)         ? 1.f : 0.f;
            const float fx1 = (x0 + 1 >= 0 && x0 + 1 < Wl) ? 1.f : 0.f;
            const float fy0 = (y0 >= 0 && y0 < Hl)         ? 1.f : 0.f;
            const float fy1 = (y0 + 1 >= 0 && y0 + 1 < Hl) ? 1.f : 0.f;

            const int xc0 = min(max(x0, 0), Wl - 1);
            const int xc1 = min(max(x0 + 1, 0), Wl - 1);
            const int yc0 = min(max(y0, 0), Hl - 1);
            const int yc1 = min(max(y0 + 1, 0), Hl - 1);

            const float cw00 = aw * wy0 * wx0 * fy0 * fx0;
            const float cw10 = aw * wy0 * wx1 * fy0 * fx1;
            const float cw01 = aw * wy1 * wx0 * fy1 * fx0;
            const float cw11 = aw * wy1 * wx1 * fy1 * fx1;
            wsum += cw00 + cw10 + cw01 + cw11;

            const size_t i00 = (size_t)(s0 + yc0 * Wl + xc0) * 64;
            const size_t i10 = (size_t)(s0 + yc0 * Wl + xc1) * 64;
            const size_t i01 = (size_t)(s0 + yc1 * Wl + xc0) * 64;
            const size_t i11 = (size_t)(s0 + yc1 * Wl + xc1) * 64;

            float4 r00a = vb[i00 + lane], r00b = vb[i00 + lane + 32];
            float4 r10a = vb[i10 + lane], r10b = vb[i10 + lane + 32];
            float4 r01a = vb[i01 + lane], r01b = vb[i01 + lane + 32];
            float4 r11a = vb[i11 + lane], r11b = vb[i11 + lane + 32];

            a0.x += cw00 * r00a.x; a0.y += cw00 * r00a.y; a0.z += cw00 * r00a.z; a0.w += cw00 * r00a.w;
            a1.x += cw00 * r00b.x; a1.y += cw00 * r00b.y; a1.z += cw00 * r00b.z; a1.w += cw00 * r00b.w;
            a0.x += cw10 * r10a.x; a0.y += cw10 * r10a.y; a0.z += cw10 * r10a.z; a0.w += cw10 * r10a.w;
            a1.x += cw10 * r10b.x; a1.y += cw10 * r10b.y; a1.z += cw10 * r10b.z; a1.w += cw10 * r10b.w;
            a0.x += cw01 * r01a.x; a0.y += cw01 * r01a.y; a0.z += cw01 * r01a.z; a0.w += cw01 * r01a.w;
            a1.x += cw01 * r01b.x; a1.y += cw01 * r01b.y; a1.z += cw01 * r01b.z; a1.w += cw01 * r01b.w;
            a0.x += cw11 * r11a.x; a0.y += cw11 * r11a.y; a0.z += cw11 * r11a.z; a0.w += cw11 * r11a.w;
            a1.x += cw11 * r11b.x; a1.y += cw11 * r11b.y; a1.z += cw11 * r11b.z; a1.w += cw11 * r11b.w;
        }
    }

    float4* rr = (float4*)(raw + ((size_t)bq * H_ + h) * D_);
    rr[lane]      = a0;
    rr[lane + 32] = a1;
    if (lane == 0) wsumb[(size_t)bq * H_ + h] = wsum;
}

// ---------------------------------------------------------------------------
// Launch
// ---------------------------------------------------------------------------
extern "C" void kernel_launch(void* const* d_in, const int* in_sizes, int n_in,
                              void* d_out, int out_size)
{
    const float* query = (const float*)d_in[0];
    const float* rp    = (const float*)d_in[1];
    const float* value = (const float*)d_in[2];
    const float* Wv    = (const float*)d_in[5];
    const float* bv    = (const float*)d_in[6];
    const float* Woff  = (const float*)d_in[7];
    const float* boff  = (const float*)d_in[8];
    const float* Wattn = (const float*)d_in[9];
    const float* battn = (const float*)d_in[10];
    const float* Wout  = (const float*)d_in[11];
    const float* bout  = (const float*)d_in[12];
    float* out = (float*)d_out;

    float *qfb, *rawb, *wsumb, *samp, *Wqf, *bqf;
    cudaGetSymbolAddress((void**)&qfb,   g_qf);
    cudaGetSymbolAddress((void**)&rawb,  g_raw);
    cudaGetSymbolAddress((void**)&wsumb, g_wsum);
    cudaGetSymbolAddress((void**)&samp,  g_samp);
    cudaGetSymbolAddress((void**)&Wqf,   g_Wqf);
    cudaGetSymbolAddress((void**)&bqf,   g_bqf);

    const int Mq = B_ * LQ_;     // 9600 = 75 * 128

    // 0) fused padded query-side weights
    prep_weights_kernel<<<(256 * NQF + 255) / 256, 256>>>(Woff, boff, Wattn, battn, Wqf, bqf);

    // 1) fused offsets+attn: [9600,256] @ [256,320]  (3xTF32)
    gemm_tf32_kernel<64, false><<<dim3(NQF / 64, Mq / 128, 1), 256>>>(
        query, D_, 0,  Wqf, NQF, 0,  bqf, 0,  nullptr, 0, 0,  qfb, NQF, 0, D_);

    // 2) gather-only sampler -> raw [9600,8,256], wsum [9600,8]
    sample_raw_kernel<<<Mq, 256>>>(rp, qfb, value, rawb, wsumb);

    // 3) per-head block-diagonal projection (3xTF32, grid.z = head)
    //    samp[m, h*32+n] = raw[m,h,:] @ Wv[:, h*32+n] + wsum[m,h]*bv[h*32+n]
    gemm_tf32_kernel<32, true><<<dim3(1, Mq / 128, H_), 256>>>(
        rawb, H_ * D_, D_,   Wv, D_, HD_,   bv, HD_,
        wsumb, H_, 1,   samp, D_, HD_, D_);

    // 4) output projection: [9600,256] @ [256,256]  (3xTF32)
    gemm_tf32_kernel<64, false><<<dim3(D_ / 64, Mq / 128, 1), 256>>>(
        samp, D_, 0,  Wout, D_, 0,  bout, 0,  nullptr, 0, 0,  out, D_, 0, D_);
}

// round 7
// speedup vs baseline: 1.0883x; 1.0883x over previous
#include <cuda_runtime.h>
#include <mma.h>
#include <cstdint>

using namespace nvcuda;

// ---------------------------------------------------------------------------
// Problem constants
// ---------------------------------------------------------------------------
#define B_   32
#define LQ_  300
#define D_   256
#define H_   8
#define L_   3
#define P_   4
#define HD_  32
#define LV_  8400   // 80*80 + 40*40 + 20*20
#define NQF  320    // padded fused off|attn width (192 off + 96 attn + 32 pad)

// ---------------------------------------------------------------------------
// Scratch (device globals)
// ---------------------------------------------------------------------------
__device__ float g_qf  [(size_t)B_ * LQ_ * NQF];          // [9600,320]
__device__ float g_raw [(size_t)B_ * LQ_ * H_ * D_];      // [9600, 8, 256]
__device__ float g_wsum[(size_t)B_ * LQ_ * H_];           // [9600, 8]
__device__ float g_samp[(size_t)B_ * LQ_ * D_];           // [9600, 256]
__device__ float g_Wqf [256 * NQF];
__device__ float g_bqf [NQF];

// ---------------------------------------------------------------------------
// Build fused (padded) query-side weights: Wqf[256,320] = [Woff | Wattn | 0]
// ---------------------------------------------------------------------------
__global__ __launch_bounds__(256)
void prep_weights_kernel(const float* __restrict__ Woff, const float* __restrict__ boff,
                         const float* __restrict__ Wattn, const float* __restrict__ battn,
                         float* __restrict__ Wqf, float* __restrict__ bqf)
{
    int i = blockIdx.x * blockDim.x + threadIdx.x;
    if (i < 256 * NQF) {
        int k = i / NQF, j = i % NQF;
        float v = 0.f;
        if (j < 192)      v = Woff[k * 192 + j];
        else if (j < 288) v = Wattn[k * 96 + (j - 192)];
        Wqf[i] = v;
    }
    if (i < NQF) {
        float v = 0.f;
        if (i < 192)      v = boff[i];
        else if (i < 288) v = battn[i - 192];
        bqf[i] = v;
    }
}

// ---------------------------------------------------------------------------
__device__ __forceinline__ float to_tf32(float x) {
    float r;
    asm("cvt.rna.tf32.f32 %0, %1;" : "=f"(r) : "f"(x));
    return r;
}

// ---------------------------------------------------------------------------
// Lean 3xTF32 GEMM: C[M,N] = A[M,K] @ B[K,N] + bias[N]
// BM=128, BN=64, BK=32, 256 thr (8 warps, 4m x 2n). Raw fp32 staged in smem
// ONCE; hi/lo split done in fragment registers. Acc initialized from a
// replicated bias tile; results stored straight to global.
// Requires M%128==0, N%64==0, K%32==0.
// ---------------------------------------------------------------------------
__global__ __launch_bounds__(256)
void gemm_tf32r_kernel(const float* __restrict__ A, int lda,
                       const float* __restrict__ Bm, int ldb,
                       const float* __restrict__ bias,
                       float* __restrict__ C, int ldc, int K)
{
    constexpr int LDA = 36;   // 128 x 36 fp32 = 18.4 KB (row = 144B, 16B mult)
    constexpr int LDB = 68;   // 32 x 68 fp32  =  8.7 KB (row = 272B, 16B mult)

    __shared__ __align__(16) float As[128][LDA];
    __shared__ __align__(16) float Bs[32][LDB];
    __shared__ __align__(16) float BiasT[16][LDB];

    const int tid = threadIdx.x;
    const int m0  = blockIdx.y * 128;
    const int n0  = blockIdx.x * 64;
    const int w   = tid >> 5;
    const int warp_m = (w >> 1) * 32;   // 4 warps down M
    const int warp_n = (w & 1) * 32;    // 2 warps across N

    // bias tile: 16 identical rows of bias[n0..n0+63]
#pragma unroll
    for (int t = 0; t < 4; t++) {
        int idx = tid + t * 256;        // < 1024
        int r = idx >> 6, c = idx & 63;
        BiasT[r][c] = bias[n0 + c];
    }
    __syncthreads();

    wmma::fragment<wmma::accumulator, 16, 16, 8, float> acc[2][2];
#pragma unroll
    for (int mi = 0; mi < 2; mi++)
#pragma unroll
        for (int ni = 0; ni < 2; ni++)
            wmma::load_matrix_sync(acc[mi][ni],
                                   &BiasT[0][warp_n + ni * 16], LDB,
                                   wmma::mem_row_major);

    for (int k0 = 0; k0 < K; k0 += 32) {
        __syncthreads();
        // stage A 128x32 (raw fp32): 1024 float4, 4/thread
#pragma unroll
        for (int t = 0; t < 4; t++) {
            int idx = tid + t * 256;
            int row = idx >> 3, q = idx & 7;
            *(float4*)&As[row][q * 4] =
                *(const float4*)(A + (size_t)(m0 + row) * lda + k0 + q * 4);
        }
        // stage B 32x64: 512 float4, 2/thread
#pragma unroll
        for (int t = 0; t < 2; t++) {
            int idx = tid + t * 256;
            int k = idx >> 4, qn = idx & 15;
            *(float4*)&Bs[k][qn * 4] =
                *(const float4*)(Bm + (size_t)(k0 + k) * ldb + n0 + qn * 4);
        }
        __syncthreads();

#pragma unroll
        for (int kk = 0; kk < 32; kk += 8) {
            wmma::fragment<wmma::matrix_a, 16, 16, 8, wmma::precision::tf32, wmma::row_major> a_hi[2], a_lo[2];
            wmma::fragment<wmma::matrix_b, 16, 16, 8, wmma::precision::tf32, wmma::row_major> b_hi[2], b_lo[2];
#pragma unroll
            for (int mi = 0; mi < 2; mi++) {
                wmma::load_matrix_sync(a_hi[mi], &As[warp_m + mi * 16][kk], LDA);
#pragma unroll
                for (int e = 0; e < a_hi[mi].num_elements; e++) {
                    float v = a_hi[mi].x[e];
                    float h = to_tf32(v);
                    a_hi[mi].x[e] = h;
                    a_lo[mi].x[e] = to_tf32(v - h);
                }
            }
#pragma unroll
            for (int ni = 0; ni < 2; ni++) {
                wmma::load_matrix_sync(b_hi[ni], &Bs[kk][warp_n + ni * 16], LDB);
#pragma unroll
                for (int e = 0; e < b_hi[ni].num_elements; e++) {
                    float v = b_hi[ni].x[e];
                    float h = to_tf32(v);
                    b_hi[ni].x[e] = h;
                    b_lo[ni].x[e] = to_tf32(v - h);
                }
            }
#pragma unroll
            for (int mi = 0; mi < 2; mi++)
#pragma unroll
                for (int ni = 0; ni < 2; ni++) {
                    wmma::mma_sync(acc[mi][ni], a_lo[mi], b_hi[ni], acc[mi][ni]);
                    wmma::mma_sync(acc[mi][ni], a_hi[mi], b_lo[ni], acc[mi][ni]);
                    wmma::mma_sync(acc[mi][ni], a_hi[mi], b_hi[ni], acc[mi][ni]);
                }
        }
    }

    // direct global store
#pragma unroll
    for (int mi = 0; mi < 2; mi++)
#pragma unroll
        for (int ni = 0; ni < 2; ni++)
            wmma::store_matrix_sync(C + (size_t)(m0 + warp_m + mi * 16) * ldc
                                      + n0 + warp_n + ni * 16,
                                    acc[mi][ni], ldc, wmma::mem_row_major);
}

// ---------------------------------------------------------------------------
// Sampling kernel (gather only): warp <-> head, CTA <-> (b,q).  [R4, proven]
// ---------------------------------------------------------------------------
__global__ __launch_bounds__(256)
void sample_raw_kernel(const float* __restrict__ rp,
                       const float* __restrict__ qf,
                       const float* __restrict__ value,
                       float* __restrict__ raw,
                       float* __restrict__ wsumb)
{
    const int bq   = blockIdx.x;
    const int h    = threadIdx.x >> 5;
    const int lane = threadIdx.x & 31;
    const int b    = bq / LQ_;

    const float* al = qf + (size_t)bq * NQF + 192 + h * (L_ * P_);
    float w[L_ * P_];
    float mx = -1e30f;
#pragma unroll
    for (int i = 0; i < L_ * P_; i++) { w[i] = al[i]; mx = fmaxf(mx, w[i]); }
    float ssum = 0.f;
#pragma unroll
    for (int i = 0; i < L_ * P_; i++) { w[i] = __expf(w[i] - mx); ssum += w[i]; }
    const float inv = 1.f / ssum;

    const float* offp = qf + (size_t)bq * NQF + h * (L_ * P_ * 2);
    const float* rpp  = rp + (size_t)bq * (L_ * 4);
    const float4* vb  = (const float4*)(value + (size_t)b * LV_ * D_);

    float4 a0 = make_float4(0.f, 0.f, 0.f, 0.f);
    float4 a1 = make_float4(0.f, 0.f, 0.f, 0.f);
    float wsum = 0.f;

    const int HsA[3] = {80, 40, 20};
    const int stA[3] = {0, 6400, 8000};

#pragma unroll
    for (int l = 0; l < L_; l++) {
        const float cx = rpp[l * 4 + 0];
        const float cy = rpp[l * 4 + 1];
        const float hw = rpp[l * 4 + 2] * 0.5f;
        const float hh = rpp[l * 4 + 3] * 0.5f;
        const int Wl = HsA[l], Hl = HsA[l], s0 = stA[l];

#pragma unroll
        for (int p = 0; p < P_; p++) {
            const float lx = cx + offp[(l * P_ + p) * 2 + 0] * hw;
            const float ly = cy + offp[(l * P_ + p) * 2 + 1] * hh;
            const float x = lx * (float)Wl - 0.5f;
            const float y = ly * (float)Hl - 0.5f;
            const float x0f = floorf(x), y0f = floorf(y);
            const int   x0 = (int)x0f,  y0 = (int)y0f;
            const float wx1 = x - x0f, wx0 = 1.f - wx1;
            const float wy1 = y - y0f, wy0 = 1.f - wy1;
            const float aw = w[l * P_ + p] * inv;

            const float fx0 = (x0 >= 0 && x0 < Wl)         ? 1.f : 0.f;
            const float fx1 = (x0 + 1 >= 0 && x0 + 1 < Wl) ? 1.f : 0.f;
            const float fy0 = (y0 >= 0 && y0 < Hl)         ? 1.f : 0.f;
            const float fy1 = (y0 + 1 >= 0 && y0 + 1 < Hl) ? 1.f : 0.f;

            const int xc0 = min(max(x0, 0), Wl - 1);
            const int xc1 = min(max(x0 + 1, 0), Wl - 1);
            const int yc0 = min(max(y0, 0), Hl - 1);
            const int yc1 = min(max(y0 + 1, 0), Hl - 1);

            const float cw00 = aw * wy0 * wx0 * fy0 * fx0;
            const float cw10 = aw * wy0 * wx1 * fy0 * fx1;
            const float cw01 = aw * wy1 * wx0 * fy1 * fx0;
            const float cw11 = aw * wy1 * wx1 * fy1 * fx1;
            wsum += cw00 + cw10 + cw01 + cw11;

            const size_t i00 = (size_t)(s0 + yc0 * Wl + xc0) * 64;
            const size_t i10 = (size_t)(s0 + yc0 * Wl + xc1) * 64;
            const size_t i01 = (size_t)(s0 + yc1 * Wl + xc0) * 64;
            const size_t i11 = (size_t)(s0 + yc1 * Wl + xc1) * 64;

            float4 r00a = vb[i00 + lane], r00b = vb[i00 + lane + 32];
            float4 r10a = vb[i10 + lane], r10b = vb[i10 + lane + 32];
            float4 r01a = vb[i01 + lane], r01b = vb[i01 + lane + 32];
            float4 r11a = vb[i11 + lane], r11b = vb[i11 + lane + 32];

            a0.x += cw00 * r00a.x; a0.y += cw00 * r00a.y; a0.z += cw00 * r00a.z; a0.w += cw00 * r00a.w;
            a1.x += cw00 * r00b.x; a1.y += cw00 * r00b.y; a1.z += cw00 * r00b.z; a1.w += cw00 * r00b.w;
            a0.x += cw10 * r10a.x; a0.y += cw10 * r10a.y; a0.z += cw10 * r10a.z; a0.w += cw10 * r10a.w;
            a1.x += cw10 * r10b.x; a1.y += cw10 * r10b.y; a1.z += cw10 * r10b.z; a1.w += cw10 * r10b.w;
            a0.x += cw01 * r01a.x; a0.y += cw01 * r01a.y; a0.z += cw01 * r01a.z; a0.w += cw01 * r01a.w;
            a1.x += cw01 * r01b.x; a1.y += cw01 * r01b.y; a1.z += cw01 * r01b.z; a1.w += cw01 * r01b.w;
            a0.x += cw11 * r11a.x; a0.y += cw11 * r11a.y; a0.z += cw11 * r11a.z; a0.w += cw11 * r11a.w;
            a1.x += cw11 * r11b.x; a1.y += cw11 * r11b.y; a1.z += cw11 * r11b.z; a1.w += cw11 * r11b.w;
        }
    }

    float4* rr = (float4*)(raw + ((size_t)bq * H_ + h) * D_);
    rr[lane]      = a0;
    rr[lane + 32] = a1;
    if (lane == 0) wsumb[(size_t)bq * H_ + h] = wsum;
}

// ---------------------------------------------------------------------------
// Per-head block-diagonal projection (R4 fp32, proven 45us)
// ---------------------------------------------------------------------------
__global__ __launch_bounds__(256)
void proj_head_kernel(const float* __restrict__ raw,
                      const float* __restrict__ wsumb,
                      const float* __restrict__ Wv,
                      const float* __restrict__ bv,
                      float* __restrict__ samp)
{
    __shared__ __align__(16) float As[32][132];
    __shared__ __align__(16) float Bs[32][32];

    const int h   = blockIdx.y;
    const int m0  = blockIdx.x * 128;
    const int tid = threadIdx.x;
    const int ty  = tid >> 3;
    const int tx  = tid & 7;

    const int am  = tid >> 3;
    const int akq = tid & 7;
    const int blk = tid >> 3;
    const int bnq = tid & 7;

    float acc[4][4];
#pragma unroll
    for (int i = 0; i < 4; i++)
#pragma unroll
        for (int j = 0; j < 4; j++) acc[i][j] = 0.f;

    const float* Ab = raw + ((size_t)m0 * H_ + h) * D_;
    const float* Bb = Wv + h * HD_;

    for (int k0 = 0; k0 < D_; k0 += 32) {
#pragma unroll
        for (int t = 0; t < 4; t++) {
            int m = am + t * 32;
            float4 v = *(const float4*)(Ab + (size_t)m * (H_ * D_) + k0 + akq * 4);
            As[akq * 4 + 0][m] = v.x;
            As[akq * 4 + 1][m] = v.y;
            As[akq * 4 + 2][m] = v.z;
            As[akq * 4 + 3][m] = v.w;
        }
        *(float4*)&Bs[blk][bnq * 4] =
            *(const float4*)(Bb + (size_t)(k0 + blk) * D_ + bnq * 4);
        __syncthreads();

#pragma unroll
        for (int k = 0; k < 32; k++) {
            float4 a = *(const float4*)&As[k][ty * 4];
            float4 b = *(const float4*)&Bs[k][tx * 4];
            acc[0][0] += a.x * b.x; acc[0][1] += a.x * b.y; acc[0][2] += a.x * b.z; acc[0][3] += a.x * b.w;
            acc[1][0] += a.y * b.x; acc[1][1] += a.y * b.y; acc[1][2] += a.y * b.z; acc[1][3] += a.y * b.w;
            acc[2][0] += a.z * b.x; acc[2][1] += a.z * b.y; acc[2][2] += a.z * b.z; acc[2][3] += a.z * b.w;
            acc[3][0] += a.w * b.x; acc[3][1] += a.w * b.y; acc[3][2] += a.w * b.z; acc[3][3] += a.w * b.w;
        }
        __syncthreads();
    }

    float4 bvv = *(const float4*)(bv + h * HD_ + tx * 4);
#pragma unroll
    for (int i = 0; i < 4; i++) {
        int m = m0 + ty * 4 + i;
        float ws = wsumb[(size_t)m * H_ + h];
        float4 o = make_float4(acc[i][0] + ws * bvv.x, acc[i][1] + ws * bvv.y,
                               acc[i][2] + ws * bvv.z, acc[i][3] + ws * bvv.w);
        *(float4*)(samp + (size_t)m * D_ + h * HD_ + tx * 4) = o;
    }
}

// ---------------------------------------------------------------------------
// Launch
// ---------------------------------------------------------------------------
extern "C" void kernel_launch(void* const* d_in, const int* in_sizes, int n_in,
                              void* d_out, int out_size)
{
    const float* query = (const float*)d_in[0];
    const float* rp    = (const float*)d_in[1];
    const float* value = (const float*)d_in[2];
    const float* Wv    = (const float*)d_in[5];
    const float* bv    = (const float*)d_in[6];
    const float* Woff  = (const float*)d_in[7];
    const float* boff  = (const float*)d_in[8];
    const float* Wattn = (const float*)d_in[9];
    const float* battn = (const float*)d_in[10];
    const float* Wout  = (const float*)d_in[11];
    const float* bout  = (const float*)d_in[12];
    float* out = (float*)d_out;

    float *qfb, *rawb, *wsumb, *samp, *Wqf, *bqf;
    cudaGetSymbolAddress((void**)&qfb,   g_qf);
    cudaGetSymbolAddress((void**)&rawb,  g_raw);
    cudaGetSymbolAddress((void**)&wsumb, g_wsum);
    cudaGetSymbolAddress((void**)&samp,  g_samp);
    cudaGetSymbolAddress((void**)&Wqf,   g_Wqf);
    cudaGetSymbolAddress((void**)&bqf,   g_bqf);

    const int Mq = B_ * LQ_;     // 9600 = 75 * 128

    // 0) fused padded query-side weights
    prep_weights_kernel<<<(256 * NQF + 255) / 256, 256>>>(Woff, boff, Wattn, battn, Wqf, bqf);

    // 1) fused offsets+attn: [9600,256] @ [256,320]  (3xTF32, in-reg split)
    gemm_tf32r_kernel<<<dim3(NQF / 64, Mq / 128), 256>>>(
        query, D_, Wqf, NQF, bqf, qfb, NQF, D_);

    // 2) gather-only sampler -> raw [9600,8,256], wsum [9600,8]
    sample_raw_kernel<<<Mq, 256>>>(rp, qfb, value, rawb, wsumb);

    // 3) per-head projection (fp32) -> samp [9600,256]
    proj_head_kernel<<<dim3(Mq / 128, H_), 256>>>(rawb, wsumb, Wv, bv, samp);

    // 4) output projection: [9600,256] @ [256,256]  (3xTF32, in-reg split)
    gemm_tf32r_kernel<<<dim3(D_ / 64, Mq / 128), 256>>>(
        samp, D_, Wout, D_, bout, out, D_, D_);
}

// round 8
// speedup vs baseline: 1.2978x; 1.1925x over previous
#include <cuda_runtime.h>
#include <cstdint>

// ---------------------------------------------------------------------------
// Problem constants
// ---------------------------------------------------------------------------
#define B_   32
#define LQ_  300
#define D_   256
#define H_   8
#define L_   3
#define P_   4
#define HD_  32
#define LV_  8400   // 80*80 + 40*40 + 20*20
#define NQF  320    // padded fused off|attn width (192 off + 96 attn + 32 pad)

// ---------------------------------------------------------------------------
// Scratch (device globals)
// ---------------------------------------------------------------------------
__device__ float g_qf  [(size_t)B_ * LQ_ * NQF];          // [9600,320]
__device__ float g_raw [(size_t)B_ * LQ_ * H_ * D_];      // [9600, 8, 256]
__device__ float g_wsum[(size_t)B_ * LQ_ * H_];           // [9600, 8]
__device__ float g_samp[(size_t)B_ * LQ_ * D_];           // [9600, 256]
__device__ float g_Wqf [256 * NQF];
__device__ float g_bqf [NQF];

// ---------------------------------------------------------------------------
// Build fused (padded) query-side weights: Wqf[256,320] = [Woff | Wattn | 0]
// ---------------------------------------------------------------------------
__global__ __launch_bounds__(256)
void prep_weights_kernel(const float* __restrict__ Woff, const float* __restrict__ boff,
                         const float* __restrict__ Wattn, const float* __restrict__ battn,
                         float* __restrict__ Wqf, float* __restrict__ bqf)
{
    int i = blockIdx.x * blockDim.x + threadIdx.x;
    if (i < 256 * NQF) {
        int k = i / NQF, j = i % NQF;
        float v = 0.f;
        if (j < 192)      v = Woff[k * 192 + j];
        else if (j < 288) v = Wattn[k * 96 + (j - 192)];
        Wqf[i] = v;
    }
    if (i < NQF) {
        float v = 0.f;
        if (i < 192)      v = boff[i];
        else if (i < 288) v = battn[i - 192];
        bqf[i] = v;
    }
}

// ---------------------------------------------------------------------------
// Tiled fp32 GEMM, no guards (R4, proven): C[M,N] = A[M,K] @ W[K,N] + bias[N]
// BM=128, BN=64, BK=32; 256 threads; 8x4 micro-tile.
// ---------------------------------------------------------------------------
__global__ __launch_bounds__(256)
void gemm_bias128(const float* __restrict__ A, const float* __restrict__ W,
                  const float* __restrict__ bias, float* __restrict__ C,
                  int N, int K)
{
    __shared__ __align__(16) float As[32][132];
    __shared__ __align__(16) float Bs[32][64];

    const int tid = threadIdx.x;
    const int m0  = blockIdx.y * 128;
    const int n0  = blockIdx.x * 64;
    const int ty  = tid >> 4;
    const int tx  = tid & 15;

    const int am  = tid >> 3;
    const int akq = tid & 7;
    const int bk  = tid >> 4;
    const int bnq = tid & 15;

    float acc[8][4];
#pragma unroll
    for (int i = 0; i < 8; i++)
#pragma unroll
        for (int j = 0; j < 4; j++) acc[i][j] = 0.f;

    for (int k0 = 0; k0 < K; k0 += 32) {
#pragma unroll
        for (int t = 0; t < 4; t++) {
            int m = am + t * 32;
            float4 v = *(const float4*)(A + (size_t)(m0 + m) * K + k0 + akq * 4);
            As[akq * 4 + 0][m] = v.x;
            As[akq * 4 + 1][m] = v.y;
            As[akq * 4 + 2][m] = v.z;
            As[akq * 4 + 3][m] = v.w;
        }
#pragma unroll
        for (int t = 0; t < 2; t++) {
            int k = bk + t * 16;
            *(float4*)&Bs[k][bnq * 4] =
                *(const float4*)(W + (size_t)(k0 + k) * N + n0 + bnq * 4);
        }
        __syncthreads();

#pragma unroll
        for (int k = 0; k < 32; k++) {
            float4 a0 = *(const float4*)&As[k][ty * 8];
            float4 a1 = *(const float4*)&As[k][ty * 8 + 4];
            float4 b  = *(const float4*)&Bs[k][tx * 4];
            float av[8] = {a0.x, a0.y, a0.z, a0.w, a1.x, a1.y, a1.z, a1.w};
#pragma unroll
            for (int i = 0; i < 8; i++) {
                acc[i][0] += av[i] * b.x;
                acc[i][1] += av[i] * b.y;
                acc[i][2] += av[i] * b.z;
                acc[i][3] += av[i] * b.w;
            }
        }
        __syncthreads();
    }

    float4 bb = *(const float4*)(bias + n0 + tx * 4);
#pragma unroll
    for (int i = 0; i < 8; i++) {
        int m = m0 + ty * 8 + i;
        float4 o = make_float4(acc[i][0] + bb.x, acc[i][1] + bb.y,
                               acc[i][2] + bb.z, acc[i][3] + bb.w);
        *(float4*)(C + (size_t)m * N + n0 + tx * 4) = o;
    }
}

// ---------------------------------------------------------------------------
// Sampling kernel, point-parallel geometry precompute.
// Warp <-> (bq, h). Lane p<12 computes point p's softmax weight, bilinear
// corner weights (x4) and corner indices (x4); warp-shfl softmax; gather
// loop broadcasts via shfl and does only LDG+FMA with 32-bit addressing.
// ---------------------------------------------------------------------------
__global__ __launch_bounds__(256)
void sample_raw_kernel(const float* __restrict__ rp,
                       const float* __restrict__ qf,     // [9600,320]
                       const float* __restrict__ value,  // [B, LV, 256]
                       float* __restrict__ raw,          // [9600, 8, 256]
                       float* __restrict__ wsumb)        // [9600, 8]
{
    const int bq   = blockIdx.x;
    const int h    = threadIdx.x >> 5;
    const int lane = threadIdx.x & 31;
    const int b    = bq / LQ_;

    const float4* vb = (const float4*)(value + (size_t)b * LV_ * D_);

    // ---- softmax over 12 logits, one per lane (lanes 12..31 padded) ----
    float logit = -1e30f;
    if (lane < 12)
        logit = qf[bq * NQF + 192 + h * 12 + lane];
    float mx = logit;
#pragma unroll
    for (int s = 16; s; s >>= 1) mx = fmaxf(mx, __shfl_xor_sync(0xffffffffu, mx, s));
    float e = (lane < 12) ? __expf(logit - mx) : 0.f;
    float ssum = e;
#pragma unroll
    for (int s = 16; s; s >>= 1) ssum += __shfl_xor_sync(0xffffffffu, ssum, s);
    const float aw = e / ssum;

    // ---- per-point geometry (lane = point id) ----
    float cw0 = 0.f, cw1 = 0.f, cw2 = 0.f, cw3 = 0.f;
    int   i0 = 0, i1 = 0, i2 = 0, i3 = 0;
    float wsp = 0.f;

    if (lane < 12) {
        const int l  = lane >> 2;                       // level
        const int Wl = (l == 0) ? 80 : ((l == 1) ? 40 : 20);
        const int s0 = (l == 0) ? 0  : ((l == 1) ? 6400 : 8000);

        const float* rpp  = rp + bq * 12 + l * 4;       // [B,LQ,L,4]
        const float cx = rpp[0], cy = rpp[1];
        const float hw = rpp[2] * 0.5f, hh = rpp[3] * 0.5f;

        const float* offp = qf + bq * NQF + h * 24 + lane * 2;
        const float lx = cx + offp[0] * hw;
        const float ly = cy + offp[1] * hh;

        const float fw = (float)Wl;
        const float x = lx * fw - 0.5f;
        const float y = ly * fw - 0.5f;
        const float x0f = floorf(x), y0f = floorf(y);
        const int   x0 = (int)x0f,  y0 = (int)y0f;
        const float wx1 = x - x0f, wx0 = 1.f - wx1;
        const float wy1 = y - y0f, wy0 = 1.f - wy1;

        const float fx0 = (x0 >= 0 && x0 < Wl)         ? 1.f : 0.f;
        const float fx1 = (x0 + 1 >= 0 && x0 + 1 < Wl) ? 1.f : 0.f;
        const float fy0 = (y0 >= 0 && y0 < Wl)         ? 1.f : 0.f;
        const float fy1 = (y0 + 1 >= 0 && y0 + 1 < Wl) ? 1.f : 0.f;

        const int xc0 = min(max(x0, 0), Wl - 1);
        const int xc1 = min(max(x0 + 1, 0), Wl - 1);
        const int yc0 = min(max(y0, 0), Wl - 1);
        const int yc1 = min(max(y0 + 1, 0), Wl - 1);

        cw0 = aw * wy0 * wx0 * fy0 * fx0;
        cw1 = aw * wy0 * wx1 * fy0 * fx1;
        cw2 = aw * wy1 * wx0 * fy1 * fx0;
        cw3 = aw * wy1 * wx1 * fy1 * fx1;
        wsp = cw0 + cw1 + cw2 + cw3;

        i0 = (s0 + yc0 * Wl + xc0) * 64;                // float4 units
        i1 = (s0 + yc0 * Wl + xc1) * 64;
        i2 = (s0 + yc1 * Wl + xc0) * 64;
        i3 = (s0 + yc1 * Wl + xc1) * 64;
    }

    float wsum = wsp;
#pragma unroll
    for (int s = 16; s; s >>= 1) wsum += __shfl_xor_sync(0xffffffffu, wsum, s);

    // ---- gather loop: broadcast point data, 8x LDG.128 + 32 FMA per point ----
    float4 a0 = make_float4(0.f, 0.f, 0.f, 0.f);
    float4 a1 = make_float4(0.f, 0.f, 0.f, 0.f);

#pragma unroll
    for (int p = 0; p < 12; p++) {
        const float c0 = __shfl_sync(0xffffffffu, cw0, p);
        const float c1 = __shfl_sync(0xffffffffu, cw1, p);
        const float c2 = __shfl_sync(0xffffffffu, cw2, p);
        const float c3 = __shfl_sync(0xffffffffu, cw3, p);
        const int   j0 = __shfl_sync(0xffffffffu, i0, p) + lane;
        const int   j1 = __shfl_sync(0xffffffffu, i1, p) + lane;
        const int   j2 = __shfl_sync(0xffffffffu, i2, p) + lane;
        const int   j3 = __shfl_sync(0xffffffffu, i3, p) + lane;

        float4 r0a = vb[j0], r0b = vb[j0 + 32];
        float4 r1a = vb[j1], r1b = vb[j1 + 32];
        float4 r2a = vb[j2], r2b = vb[j2 + 32];
        float4 r3a = vb[j3], r3b = vb[j3 + 32];

        a0.x += c0 * r0a.x; a0.y += c0 * r0a.y; a0.z += c0 * r0a.z; a0.w += c0 * r0a.w;
        a1.x += c0 * r0b.x; a1.y += c0 * r0b.y; a1.z += c0 * r0b.z; a1.w += c0 * r0b.w;
        a0.x += c1 * r1a.x; a0.y += c1 * r1a.y; a0.z += c1 * r1a.z; a0.w += c1 * r1a.w;
        a1.x += c1 * r1b.x; a1.y += c1 * r1b.y; a1.z += c1 * r1b.z; a1.w += c1 * r1b.w;
        a0.x += c2 * r2a.x; a0.y += c2 * r2a.y; a0.z += c2 * r2a.z; a0.w += c2 * r2a.w;
        a1.x += c2 * r2b.x; a1.y += c2 * r2b.y; a1.z += c2 * r2b.z; a1.w += c2 * r2b.w;
        a0.x += c3 * r3a.x; a0.y += c3 * r3a.y; a0.z += c3 * r3a.z; a0.w += c3 * r3a.w;
        a1.x += c3 * r3b.x; a1.y += c3 * r3b.y; a1.z += c3 * r3b.z; a1.w += c3 * r3b.w;
    }

    float4* rr = (float4*)(raw + ((size_t)bq * H_ + h) * D_);
    rr[lane]      = a0;
    rr[lane + 32] = a1;
    if (lane == 0) wsumb[(size_t)bq * H_ + h] = wsum;
}

// ---------------------------------------------------------------------------
// Per-head block-diagonal projection (R4 fp32, proven 45us)
// ---------------------------------------------------------------------------
__global__ __launch_bounds__(256)
void proj_head_kernel(const float* __restrict__ raw,
                      const float* __restrict__ wsumb,
                      const float* __restrict__ Wv,
                      const float* __restrict__ bv,
                      float* __restrict__ samp)
{
    __shared__ __align__(16) float As[32][132];
    __shared__ __align__(16) float Bs[32][32];

    const int h   = blockIdx.y;
    const int m0  = blockIdx.x * 128;
    const int tid = threadIdx.x;
    const int ty  = tid >> 3;
    const int tx  = tid & 7;

    const int am  = tid >> 3;
    const int akq = tid & 7;
    const int blk = tid >> 3;
    const int bnq = tid & 7;

    float acc[4][4];
#pragma unroll
    for (int i = 0; i < 4; i++)
#pragma unroll
        for (int j = 0; j < 4; j++) acc[i][j] = 0.f;

    const float* Ab = raw + ((size_t)m0 * H_ + h) * D_;
    const float* Bb = Wv + h * HD_;

    for (int k0 = 0; k0 < D_; k0 += 32) {
#pragma unroll
        for (int t = 0; t < 4; t++) {
            int m = am + t * 32;
            float4 v = *(const float4*)(Ab + (size_t)m * (H_ * D_) + k0 + akq * 4);
            As[akq * 4 + 0][m] = v.x;
            As[akq * 4 + 1][m] = v.y;
            As[akq * 4 + 2][m] = v.z;
            As[akq * 4 + 3][m] = v.w;
        }
        *(float4*)&Bs[blk][bnq * 4] =
            *(const float4*)(Bb + (size_t)(k0 + blk) * D_ + bnq * 4);
        __syncthreads();

#pragma unroll
        for (int k = 0; k < 32; k++) {
            float4 a = *(const float4*)&As[k][ty * 4];
            float4 b = *(const float4*)&Bs[k][tx * 4];
            acc[0][0] += a.x * b.x; acc[0][1] += a.x * b.y; acc[0][2] += a.x * b.z; acc[0][3] += a.x * b.w;
            acc[1][0] += a.y * b.x; acc[1][1] += a.y * b.y; acc[1][2] += a.y * b.z; acc[1][3] += a.y * b.w;
            acc[2][0] += a.z * b.x; acc[2][1] += a.z * b.y; acc[2][2] += a.z * b.z; acc[2][3] += a.z * b.w;
            acc[3][0] += a.w * b.x; acc[3][1] += a.w * b.y; acc[3][2] += a.w * b.z; acc[3][3] += a.w * b.w;
        }
        __syncthreads();
    }

    float4 bvv = *(const float4*)(bv + h * HD_ + tx * 4);
#pragma unroll
    for (int i = 0; i < 4; i++) {
        int m = m0 + ty * 4 + i;
        float ws = wsumb[(size_t)m * H_ + h];
        float4 o = make_float4(acc[i][0] + ws * bvv.x, acc[i][1] + ws * bvv.y,
                               acc[i][2] + ws * bvv.z, acc[i][3] + ws * bvv.w);
        *(float4*)(samp + (size_t)m * D_ + h * HD_ + tx * 4) = o;
    }
}

// ---------------------------------------------------------------------------
// Launch
// ---------------------------------------------------------------------------
extern "C" void kernel_launch(void* const* d_in, const int* in_sizes, int n_in,
                              void* d_out, int out_size)
{
    const float* query = (const float*)d_in[0];
    const float* rp    = (const float*)d_in[1];
    const float* value = (const float*)d_in[2];
    const float* Wv    = (const float*)d_in[5];
    const float* bv    = (const float*)d_in[6];
    const float* Woff  = (const float*)d_in[7];
    const float* boff  = (const float*)d_in[8];
    const float* Wattn = (const float*)d_in[9];
    const float* battn = (const float*)d_in[10];
    const float* Wout  = (const float*)d_in[11];
    const float* bout  = (const float*)d_in[12];
    float* out = (float*)d_out;

    float *qfb, *rawb, *wsumb, *samp, *Wqf, *bqf;
    cudaGetSymbolAddress((void**)&qfb,   g_qf);
    cudaGetSymbolAddress((void**)&rawb,  g_raw);
    cudaGetSymbolAddress((void**)&wsumb, g_wsum);
    cudaGetSymbolAddress((void**)&samp,  g_samp);
    cudaGetSymbolAddress((void**)&Wqf,   g_Wqf);
    cudaGetSymbolAddress((void**)&bqf,   g_bqf);

    const int Mq = B_ * LQ_;     // 9600 = 75 * 128

    // 0) fused padded query-side weights
    prep_weights_kernel<<<(256 * NQF + 255) / 256, 256>>>(Woff, boff, Wattn, battn, Wqf, bqf);

    // 1) fused offsets+attn: [9600,256] @ [256,320]
    gemm_bias128<<<dim3(NQF / 64, Mq / 128), 256>>>(query, Wqf, bqf, qfb, NQF, D_);

    // 2) gather-only sampler -> raw [9600,8,256], wsum [9600,8]
    sample_raw_kernel<<<Mq, 256>>>(rp, qfb, value, rawb, wsumb);

    // 3) per-head projection (fp32) -> samp [9600,256]
    proj_head_kernel<<<dim3(Mq / 128, H_), 256>>>(rawb, wsumb, Wv, bv, samp);

    // 4) output projection: [9600,256] @ [256,256]
    gemm_bias128<<<dim3(D_ / 64, Mq / 128), 256>>>(samp, Wout, bout, out, D_, D_);
}

// round 9
// speedup vs baseline: 1.3178x; 1.0154x over previous
#include <cuda_runtime.h>
#include <cstdint>

// ---------------------------------------------------------------------------
// Problem constants
// ---------------------------------------------------------------------------
#define B_   32
#define LQ_  300
#define D_   256
#define H_   8
#define L_   3
#define P_   4
#define HD_  32
#define LV_  8400   // 80*80 + 40*40 + 20*20
#define NQF  320    // padded fused off|attn width (192 off + 96 attn + 32 pad)

// ---------------------------------------------------------------------------
// Packed fp32x2 helpers (Blackwell FFMA2 via PTX; full fp32 precision)
// ---------------------------------------------------------------------------
__device__ __forceinline__ unsigned long long pack2(float lo, float hi) {
    unsigned long long r;
    asm("mov.b64 %0, {%1, %2};" : "=l"(r) : "r"(__float_as_uint(lo)), "r"(__float_as_uint(hi)));
    return r;
}
__device__ __forceinline__ void unpack2(unsigned long long v, float& lo, float& hi) {
    unsigned ulo, uhi;
    asm("mov.b64 {%0, %1}, %2;" : "=r"(ulo), "=r"(uhi) : "l"(v));
    lo = __uint_as_float(ulo);
    hi = __uint_as_float(uhi);
}
__device__ __forceinline__ void ffma2(unsigned long long& d,
                                      unsigned long long a, unsigned long long b) {
    asm("fma.rn.f32x2 %0, %1, %2, %0;" : "+l"(d) : "l"(a), "l"(b));
}

// ---------------------------------------------------------------------------
// Scratch (device globals)
// ---------------------------------------------------------------------------
__device__ float g_qf  [(size_t)B_ * LQ_ * NQF];          // [9600,320]
__device__ float g_raw [(size_t)B_ * LQ_ * H_ * D_];      // [9600, 8, 256]
__device__ float g_wsum[(size_t)B_ * LQ_ * H_];           // [9600, 8]
__device__ float g_samp[(size_t)B_ * LQ_ * D_];           // [9600, 256]
__device__ float g_Wqf [256 * NQF];
__device__ float g_bqf [NQF];

// ---------------------------------------------------------------------------
// Build fused (padded) query-side weights: Wqf[256,320] = [Woff | Wattn | 0]
// ---------------------------------------------------------------------------
__global__ __launch_bounds__(256)
void prep_weights_kernel(const float* __restrict__ Woff, const float* __restrict__ boff,
                         const float* __restrict__ Wattn, const float* __restrict__ battn,
                         float* __restrict__ Wqf, float* __restrict__ bqf)
{
    int i = blockIdx.x * blockDim.x + threadIdx.x;
    if (i < 256 * NQF) {
        int k = i / NQF, j = i % NQF;
        float v = 0.f;
        if (j < 192)      v = Woff[k * 192 + j];
        else if (j < 288) v = Wattn[k * 96 + (j - 192)];
        Wqf[i] = v;
    }
    if (i < NQF) {
        float v = 0.f;
        if (i < 192)      v = boff[i];
        else if (i < 288) v = battn[i - 192];
        bqf[i] = v;
    }
}

// ---------------------------------------------------------------------------
// Tiled fp32 GEMM with packed FFMA2: C[M,N] = A[M,K] @ W[K,N] + bias[N]
// BM=128, BN=64, BK=32; 256 threads; 8x4 micro-tile (per k: 3 LDS.128,
// 10 packs on alu pipe, 16 FFMA2 on fma pipe).
// Requires M%128==0, N%64==0, K%32==0.
// ---------------------------------------------------------------------------
__global__ __launch_bounds__(256)
void gemm_bias128(const float* __restrict__ A, const float* __restrict__ W,
                  const float* __restrict__ bias, float* __restrict__ C,
                  int N, int K)
{
    __shared__ __align__(16) float As[32][132];
    __shared__ __align__(16) float Bs[32][64];

    const int tid = threadIdx.x;
    const int m0  = blockIdx.y * 128;
    const int n0  = blockIdx.x * 64;
    const int ty  = tid >> 4;
    const int tx  = tid & 15;

    const int am  = tid >> 3;
    const int akq = tid & 7;
    const int bk  = tid >> 4;
    const int bnq = tid & 15;

    unsigned long long acc2[8][2];
#pragma unroll
    for (int i = 0; i < 8; i++) { acc2[i][0] = 0ull; acc2[i][1] = 0ull; }

    for (int k0 = 0; k0 < K; k0 += 32) {
#pragma unroll
        for (int t = 0; t < 4; t++) {
            int m = am + t * 32;
            float4 v = *(const float4*)(A + (size_t)(m0 + m) * K + k0 + akq * 4);
            As[akq * 4 + 0][m] = v.x;
            As[akq * 4 + 1][m] = v.y;
            As[akq * 4 + 2][m] = v.z;
            As[akq * 4 + 3][m] = v.w;
        }
#pragma unroll
        for (int t = 0; t < 2; t++) {
            int k = bk + t * 16;
            *(float4*)&Bs[k][bnq * 4] =
                *(const float4*)(W + (size_t)(k0 + k) * N + n0 + bnq * 4);
        }
        __syncthreads();

#pragma unroll
        for (int k = 0; k < 32; k++) {
            float4 a0 = *(const float4*)&As[k][ty * 8];
            float4 a1 = *(const float4*)&As[k][ty * 8 + 4];
            float4 b  = *(const float4*)&Bs[k][tx * 4];
            unsigned long long b01 = pack2(b.x, b.y);
            unsigned long long b23 = pack2(b.z, b.w);
            float av[8] = {a0.x, a0.y, a0.z, a0.w, a1.x, a1.y, a1.z, a1.w};
#pragma unroll
            for (int i = 0; i < 8; i++) {
                unsigned long long ad = pack2(av[i], av[i]);
                ffma2(acc2[i][0], ad, b01);
                ffma2(acc2[i][1], ad, b23);
            }
        }
        __syncthreads();
    }

    float4 bb = *(const float4*)(bias + n0 + tx * 4);
#pragma unroll
    for (int i = 0; i < 8; i++) {
        int m = m0 + ty * 8 + i;
        float4 o;
        unpack2(acc2[i][0], o.x, o.y);
        unpack2(acc2[i][1], o.z, o.w);
        o.x += bb.x; o.y += bb.y; o.z += bb.z; o.w += bb.w;
        *(float4*)(C + (size_t)m * N + n0 + tx * 4) = o;
    }
}

// ---------------------------------------------------------------------------
// Sampling kernel (R7, at L1-wavefront floor). Warp <-> (bq, h).
// ---------------------------------------------------------------------------
__global__ __launch_bounds__(256)
void sample_raw_kernel(const float* __restrict__ rp,
                       const float* __restrict__ qf,     // [9600,320]
                       const float* __restrict__ value,  // [B, LV, 256]
                       float* __restrict__ raw,          // [9600, 8, 256]
                       float* __restrict__ wsumb)        // [9600, 8]
{
    const int bq   = blockIdx.x;
    const int h    = threadIdx.x >> 5;
    const int lane = threadIdx.x & 31;
    const int b    = bq / LQ_;

    const float4* vb = (const float4*)(value + (size_t)b * LV_ * D_);

    // softmax over 12 logits, one per lane
    float logit = -1e30f;
    if (lane < 12)
        logit = qf[bq * NQF + 192 + h * 12 + lane];
    float mx = logit;
#pragma unroll
    for (int s = 16; s; s >>= 1) mx = fmaxf(mx, __shfl_xor_sync(0xffffffffu, mx, s));
    float e = (lane < 12) ? __expf(logit - mx) : 0.f;
    float ssum = e;
#pragma unroll
    for (int s = 16; s; s >>= 1) ssum += __shfl_xor_sync(0xffffffffu, ssum, s);
    const float aw = e / ssum;

    float cw0 = 0.f, cw1 = 0.f, cw2 = 0.f, cw3 = 0.f;
    int   i0 = 0, i1 = 0, i2 = 0, i3 = 0;
    float wsp = 0.f;

    if (lane < 12) {
        const int l  = lane >> 2;
        const int Wl = (l == 0) ? 80 : ((l == 1) ? 40 : 20);
        const int s0 = (l == 0) ? 0  : ((l == 1) ? 6400 : 8000);

        const float* rpp  = rp + bq * 12 + l * 4;
        const float cx = rpp[0], cy = rpp[1];
        const float hw = rpp[2] * 0.5f, hh = rpp[3] * 0.5f;

        const float* offp = qf + bq * NQF + h * 24 + lane * 2;
        const float lx = cx + offp[0] * hw;
        const float ly = cy + offp[1] * hh;

        const float fw = (float)Wl;
        const float x = lx * fw - 0.5f;
        const float y = ly * fw - 0.5f;
        const float x0f = floorf(x), y0f = floorf(y);
        const int   x0 = (int)x0f,  y0 = (int)y0f;
        const float wx1 = x - x0f, wx0 = 1.f - wx1;
        const float wy1 = y - y0f, wy0 = 1.f - wy1;

        const float fx0 = (x0 >= 0 && x0 < Wl)         ? 1.f : 0.f;
        const float fx1 = (x0 + 1 >= 0 && x0 + 1 < Wl) ? 1.f : 0.f;
        const float fy0 = (y0 >= 0 && y0 < Wl)         ? 1.f : 0.f;
        const float fy1 = (y0 + 1 >= 0 && y0 + 1 < Wl) ? 1.f : 0.f;

        const int xc0 = min(max(x0, 0), Wl - 1);
        const int xc1 = min(max(x0 + 1, 0), Wl - 1);
        const int yc0 = min(max(y0, 0), Wl - 1);
        const int yc1 = min(max(y0 + 1, 0), Wl - 1);

        cw0 = aw * wy0 * wx0 * fy0 * fx0;
        cw1 = aw * wy0 * wx1 * fy0 * fx1;
        cw2 = aw * wy1 * wx0 * fy1 * fx0;
        cw3 = aw * wy1 * wx1 * fy1 * fx1;
        wsp = cw0 + cw1 + cw2 + cw3;

        i0 = (s0 + yc0 * Wl + xc0) * 64;
        i1 = (s0 + yc0 * Wl + xc1) * 64;
        i2 = (s0 + yc1 * Wl + xc0) * 64;
        i3 = (s0 + yc1 * Wl + xc1) * 64;
    }

    float wsum = wsp;
#pragma unroll
    for (int s = 16; s; s >>= 1) wsum += __shfl_xor_sync(0xffffffffu, wsum, s);

    float4 a0 = make_float4(0.f, 0.f, 0.f, 0.f);
    float4 a1 = make_float4(0.f, 0.f, 0.f, 0.f);

#pragma unroll
    for (int p = 0; p < 12; p++) {
        const float c0 = __shfl_sync(0xffffffffu, cw0, p);
        const float c1 = __shfl_sync(0xffffffffu, cw1, p);
        const float c2 = __shfl_sync(0xffffffffu, cw2, p);
        const float c3 = __shfl_sync(0xffffffffu, cw3, p);
        const int   j0 = __shfl_sync(0xffffffffu, i0, p) + lane;
        const int   j1 = __shfl_sync(0xffffffffu, i1, p) + lane;
        const int   j2 = __shfl_sync(0xffffffffu, i2, p) + lane;
        const int   j3 = __shfl_sync(0xffffffffu, i3, p) + lane;

        float4 r0a = vb[j0], r0b = vb[j0 + 32];
        float4 r1a = vb[j1], r1b = vb[j1 + 32];
        float4 r2a = vb[j2], r2b = vb[j2 + 32];
        float4 r3a = vb[j3], r3b = vb[j3 + 32];

        a0.x += c0 * r0a.x; a0.y += c0 * r0a.y; a0.z += c0 * r0a.z; a0.w += c0 * r0a.w;
        a1.x += c0 * r0b.x; a1.y += c0 * r0b.y; a1.z += c0 * r0b.z; a1.w += c0 * r0b.w;
        a0.x += c1 * r1a.x; a0.y += c1 * r1a.y; a0.z += c1 * r1a.z; a0.w += c1 * r1a.w;
        a1.x += c1 * r1b.x; a1.y += c1 * r1b.y; a1.z += c1 * r1b.z; a1.w += c1 * r1b.w;
        a0.x += c2 * r2a.x; a0.y += c2 * r2a.y; a0.z += c2 * r2a.z; a0.w += c2 * r2a.w;
        a1.x += c2 * r2b.x; a1.y += c2 * r2b.y; a1.z += c2 * r2b.z; a1.w += c2 * r2b.w;
        a0.x += c3 * r3a.x; a0.y += c3 * r3a.y; a0.z += c3 * r3a.z; a0.w += c3 * r3a.w;
        a1.x += c3 * r3b.x; a1.y += c3 * r3b.y; a1.z += c3 * r3b.z; a1.w += c3 * r3b.w;
    }

    float4* rr = (float4*)(raw + ((size_t)bq * H_ + h) * D_);
    rr[lane]      = a0;
    rr[lane + 32] = a1;
    if (lane == 0) wsumb[(size_t)bq * H_ + h] = wsum;
}

// ---------------------------------------------------------------------------
// Per-head block-diagonal projection with FFMA2.
// BM=128, N=32, BK=32; 256 threads; 4x4 micro (per k: 2 LDS.128, 6 packs,
// 8 FFMA2).
// ---------------------------------------------------------------------------
__global__ __launch_bounds__(256)
void proj_head_kernel(const float* __restrict__ raw,
                      const float* __restrict__ wsumb,
                      const float* __restrict__ Wv,
                      const float* __restrict__ bv,
                      float* __restrict__ samp)
{
    __shared__ __align__(16) float As[32][132];
    __shared__ __align__(16) float Bs[32][32];

    const int h   = blockIdx.y;
    const int m0  = blockIdx.x * 128;
    const int tid = threadIdx.x;
    const int ty  = tid >> 3;
    const int tx  = tid & 7;

    const int am  = tid >> 3;
    const int akq = tid & 7;
    const int blk = tid >> 3;
    const int bnq = tid & 7;

    unsigned long long acc2[4][2];
#pragma unroll
    for (int i = 0; i < 4; i++) { acc2[i][0] = 0ull; acc2[i][1] = 0ull; }

    const float* Ab = raw + ((size_t)m0 * H_ + h) * D_;
    const float* Bb = Wv + h * HD_;

    for (int k0 = 0; k0 < D_; k0 += 32) {
#pragma unroll
        for (int t = 0; t < 4; t++) {
            int m = am + t * 32;
            float4 v = *(const float4*)(Ab + (size_t)m * (H_ * D_) + k0 + akq * 4);
            As[akq * 4 + 0][m] = v.x;
            As[akq * 4 + 1][m] = v.y;
            As[akq * 4 + 2][m] = v.z;
            As[akq * 4 + 3][m] = v.w;
        }
        *(float4*)&Bs[blk][bnq * 4] =
            *(const float4*)(Bb + (size_t)(k0 + blk) * D_ + bnq * 4);
        __syncthreads();

#pragma unroll
        for (int k = 0; k < 32; k++) {
            float4 a = *(const float4*)&As[k][ty * 4];
            float4 b = *(const float4*)&Bs[k][tx * 4];
            unsigned long long b01 = pack2(b.x, b.y);
            unsigned long long b23 = pack2(b.z, b.w);
            unsigned long long ad;
            ad = pack2(a.x, a.x); ffma2(acc2[0][0], ad, b01); ffma2(acc2[0][1], ad, b23);
            ad = pack2(a.y, a.y); ffma2(acc2[1][0], ad, b01); ffma2(acc2[1][1], ad, b23);
            ad = pack2(a.z, a.z); ffma2(acc2[2][0], ad, b01); ffma2(acc2[2][1], ad, b23);
            ad = pack2(a.w, a.w); ffma2(acc2[3][0], ad, b01); ffma2(acc2[3][1], ad, b23);
        }
        __syncthreads();
    }

    float4 bvv = *(const float4*)(bv + h * HD_ + tx * 4);
#pragma unroll
    for (int i = 0; i < 4; i++) {
        int m = m0 + ty * 4 + i;
        float ws = wsumb[(size_t)m * H_ + h];
        float4 o;
        unpack2(acc2[i][0], o.x, o.y);
        unpack2(acc2[i][1], o.z, o.w);
        o.x += ws * bvv.x; o.y += ws * bvv.y; o.z += ws * bvv.z; o.w += ws * bvv.w;
        *(float4*)(samp + (size_t)m * D_ + h * HD_ + tx * 4) = o;
    }
}

// ---------------------------------------------------------------------------
// Launch
// ---------------------------------------------------------------------------
extern "C" void kernel_launch(void* const* d_in, const int* in_sizes, int n_in,
                              void* d_out, int out_size)
{
    const float* query = (const float*)d_in[0];
    const float* rp    = (const float*)d_in[1];
    const float* value = (const float*)d_in[2];
    const float* Wv    = (const float*)d_in[5];
    const float* bv    = (const float*)d_in[6];
    const float* Woff  = (const float*)d_in[7];
    const float* boff  = (const float*)d_in[8];
    const float* Wattn = (const float*)d_in[9];
    const float* battn = (const float*)d_in[10];
    const float* Wout  = (const float*)d_in[11];
    const float* bout  = (const float*)d_in[12];
    float* out = (float*)d_out;

    float *qfb, *rawb, *wsumb, *samp, *Wqf, *bqf;
    cudaGetSymbolAddress((void**)&qfb,   g_qf);
    cudaGetSymbolAddress((void**)&rawb,  g_raw);
    cudaGetSymbolAddress((void**)&wsumb, g_wsum);
    cudaGetSymbolAddress((void**)&samp,  g_samp);
    cudaGetSymbolAddress((void**)&Wqf,   g_Wqf);
    cudaGetSymbolAddress((void**)&bqf,   g_bqf);

    const int Mq = B_ * LQ_;     // 9600 = 75 * 128

    // 0) fused padded query-side weights
    prep_weights_kernel<<<(256 * NQF + 255) / 256, 256>>>(Woff, boff, Wattn, battn, Wqf, bqf);

    // 1) fused offsets+attn: [9600,256] @ [256,320]
    gemm_bias128<<<dim3(NQF / 64, Mq / 128), 256>>>(query, Wqf, bqf, qfb, NQF, D_);

    // 2) gather-only sampler -> raw [9600,8,256], wsum [9600,8]
    sample_raw_kernel<<<Mq, 256>>>(rp, qfb, value, rawb, wsumb);

    // 3) per-head projection -> samp [9600,256]
    proj_head_kernel<<<dim3(Mq / 128, H_), 256>>>(rawb, wsumb, Wv, bv, samp);

    // 4) output projection: [9600,256] @ [256,256]
    gemm_bias128<<<dim3(D_ / 64, Mq / 128), 256>>>(samp, Wout, bout, out, D_, D_);
}